// round 5
// baseline (speedup 1.0000x reference)
#include <cuda_runtime.h>
#include <cstdint>

#define C_DIM 256
#define N_TOK 8
#define D_DIM 512
#define HW    4096
#define B_SZ  4
#define EPS   1e-6f

// ---- persistent scratch (no runtime allocation allowed) ----
__device__ float g_qp[B_SZ * D_DIM];
__device__ float g_sgp[8][B_SZ * C_DIM];
__device__ float g_sg[B_SZ * C_DIM];
__device__ float g_wovp[16][C_DIM * C_DIM];          // partial WovT over 16 d-chunks (4MB)
__device__ float g_wovgT[C_DIM * C_DIM];             // [ch][co]
__device__ float g_agg[(size_t)B_SZ * C_DIM * HW];   // 16MB

// f32x2 packed FMA (FFMA2)
#define FMA2(d, a, b, c) \
    asm("fma.rn.f32x2 %0, %1, %2, %3;" : "=l"(d) : "l"(a), "l"(b), "l"(c))

// ---------------------------------------------------------------------------
// qp[b,d] = sum_c Wq[d,c] * q[b,c]     grid (B, 8), warp per d-row
// ---------------------------------------------------------------------------
__global__ void k_qp(const float* __restrict__ q, const float* __restrict__ Wq) {
    int b = blockIdx.x, dc = blockIdx.y;
    __shared__ float qs[C_DIM];
    int tid = threadIdx.x, warp = tid >> 5, lane = tid & 31;
    qs[tid] = q[b * C_DIM + tid];
    __syncthreads();
    #pragma unroll
    for (int i = 0; i < 8; ++i) {
        int d = dc * 64 + i * 8 + warp;
        float s = 0.f;
        #pragma unroll
        for (int k = 0; k < 8; ++k) s += __ldg(&Wq[d * C_DIM + lane + k * 32]) * qs[lane + k * 32];
        #pragma unroll
        for (int o = 16; o > 0; o >>= 1) s += __shfl_xor_sync(0xffffffffu, s, o);
        if (lane == 0) g_qp[b * D_DIM + d] = s;
    }
}

// ---------------------------------------------------------------------------
// sgp[ck][b,ch] = sum_{d in 64-chunk ck} Wk[d,ch] * qp[b,d]
// ---------------------------------------------------------------------------
__global__ void k_sgp(const float* __restrict__ Wkv) {
    int b = blockIdx.x, ck = blockIdx.y, tid = threadIdx.x;
    __shared__ float qps[64];
    if (tid < 64) qps[tid] = g_qp[b * D_DIM + ck * 64 + tid];
    __syncthreads();
    float a = 0.f;
    const float* wk = Wkv + (size_t)(ck * 64) * C_DIM + tid;
    #pragma unroll 16
    for (int d = 0; d < 64; ++d) a += __ldg(wk + (size_t)d * C_DIM) * qps[d];
    g_sgp[ck][b * C_DIM + tid] = a;
}

__global__ void k_sgr(const float* __restrict__ g) {
    int b = blockIdx.x, tid = threadIdx.x;
    float s = 0.f;
    #pragma unroll
    for (int i = 0; i < 8; ++i) s += g_sgp[i][b * C_DIM + tid];
    g_sg[b * C_DIM + tid] = s * g[tid] * rsqrtf((float)D_DIM);
}

// ---------------------------------------------------------------------------
// wovp[kc][ch][co] = sum_{d in 32-chunk kc} Wo[co,d] * Wv[d,ch]
// grid (64 co-tiles x 16 k-chunks); thread = ch, 4 co per block, 32 d-iters
// ---------------------------------------------------------------------------
__global__ void k_wovp(const float* __restrict__ Wo, const float* __restrict__ Wkv) {
    int co0 = blockIdx.x * 4, kc = blockIdx.y;
    __shared__ float wo_s[4][32];
    int tid = threadIdx.x;
    if (tid < 128) {
        int r = tid >> 5, cc = tid & 31;
        wo_s[r][cc] = __ldg(&Wo[(co0 + r) * D_DIM + kc * 32 + cc]);
    }
    __syncthreads();
    const float* wv = Wkv + (size_t)(D_DIM + kc * 32) * C_DIM + tid;
    float a0 = 0.f, a1 = 0.f, a2 = 0.f, a3 = 0.f;
    #pragma unroll
    for (int d = 0; d < 32; ++d) {
        float v = __ldg(wv + (size_t)d * C_DIM);
        a0 += wo_s[0][d] * v; a1 += wo_s[1][d] * v;
        a2 += wo_s[2][d] * v; a3 += wo_s[3][d] * v;
    }
    float* o = &g_wovp[kc][tid * C_DIM + co0];
    o[0] = a0; o[1] = a1; o[2] = a2; o[3] = a3;
}

__global__ void k_wovr(const float* __restrict__ g) {
    int idx = blockIdx.x * 256 + threadIdx.x;
    float s = 0.f;
    #pragma unroll
    for (int i = 0; i < 16; ++i) s += g_wovp[i][idx];
    g_wovgT[idx] = s * g[idx >> 8];
}

// ---------------------------------------------------------------------------
// k_fuse: single pass over c. One block = 8 pixels of one batch.
// ---------------------------------------------------------------------------
#define FUSE_SMEM (2048 * 12 * 4 + (64 * 3 + 256) * 4)
__global__ void __launch_bounds__(256, 2) k_fuse(const float* __restrict__ c) {
    extern __shared__ float sh[];
    float* cs   = sh;
    float* dots = sh + 2048 * 12;
    float* invs = dots + 64;
    float* wgt  = invs + 64;
    float* sg_s = wgt + 64;

    int tid = threadIdx.x;
    int blk = blockIdx.x;
    int b = blk >> 9;
    int p0 = (blk & 511) * 8;

    sg_s[tid] = g_sg[b * C_DIM + tid];
    const float* cb = c + (size_t)b * N_TOK * C_DIM * HW;

    #pragma unroll
    for (int k = 0; k < 16; ++k) {
        int idx = tid + k * 256;
        int row = idx >> 1, f = idx & 1;
        float4 v = __ldg((const float4*)(cb + (size_t)row * HW + p0) + f);
        *(float4*)(cs + row * 12 + f * 4) = v;
    }
    __syncthreads();

    {
        int sub = tid & 3, pair = tid >> 2;
        int n = pair >> 3, p = pair & 7;
        float ss = 0.f, dt = 0.f;
        #pragma unroll 8
        for (int ch = sub; ch < C_DIM; ch += 4) {
            float v = cs[(n * C_DIM + ch) * 12 + p];
            ss += v * v;
            dt += v * sg_s[ch];
        }
        ss += __shfl_xor_sync(0xffffffffu, ss, 1);
        dt += __shfl_xor_sync(0xffffffffu, dt, 1);
        ss += __shfl_xor_sync(0xffffffffu, ss, 2);
        dt += __shfl_xor_sync(0xffffffffu, dt, 2);
        if (sub == 0) {
            float inv = rsqrtf(ss * (1.0f / C_DIM) + EPS);
            dots[pair] = dt * inv;
            invs[pair] = inv;
        }
    }
    __syncthreads();
    if (tid < 64) {
        int pp = tid & 7;
        float m = dots[pp];
        #pragma unroll
        for (int i = 1; i < N_TOK; ++i) m = fmaxf(m, dots[i * 8 + pp]);
        float sum = 0.f;
        #pragma unroll
        for (int i = 0; i < N_TOK; ++i) sum += __expf(dots[i * 8 + pp] - m);
        wgt[tid] = __expf(dots[tid] - m) / sum * invs[tid];
    }
    __syncthreads();

    {
        float4 a0 = make_float4(0.f, 0.f, 0.f, 0.f);
        float4 a1 = make_float4(0.f, 0.f, 0.f, 0.f);
        #pragma unroll
        for (int i = 0; i < N_TOK; ++i) {
            const float* r = cs + (i * C_DIM + tid) * 12;
            float4 v0 = *(const float4*)r;
            float4 v1 = *(const float4*)(r + 4);
            const float* w = wgt + i * 8;
            a0.x += w[0] * v0.x; a0.y += w[1] * v0.y; a0.z += w[2] * v0.z; a0.w += w[3] * v0.w;
            a1.x += w[4] * v1.x; a1.y += w[5] * v1.y; a1.z += w[6] * v1.z; a1.w += w[7] * v1.w;
        }
        float* ag = g_agg + (size_t)(b * C_DIM + tid) * HW + p0;
        *(float4*)ag = a0;
        *(float4*)(ag + 4) = a1;
    }
}

// ---------------------------------------------------------------------------
// k_gemm: 64co x 128p tiles, K-chunks of 32, double-buffered, FFMA2.
// Weight smem loads as LDS.128 broadcast (8 wf/warp-ch instead of 12).
// ---------------------------------------------------------------------------
#define TP  128
#define TCO 64
#define KC  32
__global__ void __launch_bounds__(256) k_gemm(const float* __restrict__ bo,
                                              float* __restrict__ out) {
    __shared__ float aggS[2][KC][TP];
    __shared__ unsigned long long wovD[2][KC][TCO];
    int tid = threadIdx.x;
    int blk = blockIdx.x;
    int pt = blk & 31, ct = (blk >> 5) & 3, b = blk >> 7;
    int p0 = pt * TP, co0 = ct * TCO;
    int tx = tid & 31, ty = tid >> 5;
    int po = tx * 4, coo = ty * 8;

    unsigned long long acc[8][2];
    #pragma unroll
    for (int i = 0; i < 8; ++i) { acc[i][0] = 0ull; acc[i][1] = 0ull; }

    const float* aggB = g_agg + (size_t)b * C_DIM * HW + p0;

    #define STAGE(BUF, CH0) do {                                               \
        _Pragma("unroll")                                                      \
        for (int k = 0; k < 4; ++k) {                                          \
            int idx = tid + k * 256;                                           \
            int ch = idx >> 5, f = idx & 31;                                   \
            *(float4*)&aggS[BUF][ch][f * 4] =                                  \
                __ldg((const float4*)(aggB + (size_t)((CH0) + ch) * HW) + f);  \
        }                                                                      \
        _Pragma("unroll")                                                      \
        for (int k = 0; k < 8; ++k) {                                          \
            int idx = tid + k * 256;                                           \
            int ch = idx >> 6, co = idx & 63;                                  \
            float w = __ldg(&g_wovgT[((CH0) + ch) * C_DIM + co0 + co]);        \
            unsigned long long pk;                                             \
            asm("mov.b64 %0, {%1, %1};" : "=l"(pk) : "r"(__float_as_uint(w))); \
            wovD[BUF][ch][co] = pk;                                            \
        }                                                                      \
    } while (0)

    STAGE(0, 0);
    #pragma unroll
    for (int ck = 0; ck < 8; ++ck) {
        __syncthreads();
        if (ck < 7) STAGE((ck + 1) & 1, (ck + 1) * KC);
        int cur = ck & 1;
        #pragma unroll
        for (int ch = 0; ch < KC; ++ch) {
            ulonglong2 ap = *(const ulonglong2*)&aggS[cur][ch][po];
            const ulonglong2* wp2 = (const ulonglong2*)&wovD[cur][ch][coo];
            ulonglong2 w01 = wp2[0], w23 = wp2[1], w45 = wp2[2], w67 = wp2[3];
            FMA2(acc[0][0], w01.x, ap.x, acc[0][0]); FMA2(acc[0][1], w01.x, ap.y, acc[0][1]);
            FMA2(acc[1][0], w01.y, ap.x, acc[1][0]); FMA2(acc[1][1], w01.y, ap.y, acc[1][1]);
            FMA2(acc[2][0], w23.x, ap.x, acc[2][0]); FMA2(acc[2][1], w23.x, ap.y, acc[2][1]);
            FMA2(acc[3][0], w23.y, ap.x, acc[3][0]); FMA2(acc[3][1], w23.y, ap.y, acc[3][1]);
            FMA2(acc[4][0], w45.x, ap.x, acc[4][0]); FMA2(acc[4][1], w45.x, ap.y, acc[4][1]);
            FMA2(acc[5][0], w45.y, ap.x, acc[5][0]); FMA2(acc[5][1], w45.y, ap.y, acc[5][1]);
            FMA2(acc[6][0], w67.x, ap.x, acc[6][0]); FMA2(acc[6][1], w67.x, ap.y, acc[6][1]);
            FMA2(acc[7][0], w67.y, ap.x, acc[7][0]); FMA2(acc[7][1], w67.y, ap.y, acc[7][1]);
        }
    }
    #undef STAGE

    float* ob = out + ((size_t)b * C_DIM + co0 + coo) * HW + p0 + po;
    #pragma unroll
    for (int i = 0; i < 8; ++i) {
        float bb = __ldg(&bo[co0 + coo + i]);
        unsigned lx, ly, hx, hy;
        asm("mov.b64 {%0, %1}, %2;" : "=r"(lx), "=r"(ly) : "l"(acc[i][0]));
        asm("mov.b64 {%0, %1}, %2;" : "=r"(hx), "=r"(hy) : "l"(acc[i][1]));
        float4 r = make_float4(__uint_as_float(lx) + bb, __uint_as_float(ly) + bb,
                               __uint_as_float(hx) + bb, __uint_as_float(hy) + bb);
        *(float4*)(ob + (size_t)i * HW) = r;
    }
}

extern "C" void kernel_launch(void* const* d_in, const int* in_sizes, int n_in,
                              void* d_out, int out_size) {
    const float* q   = (const float*)d_in[0];
    const float* c   = (const float*)d_in[1];
    const float* g   = (const float*)d_in[2];
    const float* Wq  = (const float*)d_in[3];
    const float* Wkv = (const float*)d_in[4];
    const float* Wo  = (const float*)d_in[5];
    const float* bo  = (const float*)d_in[6];
    float* out = (float*)d_out;

    cudaFuncSetAttribute(k_fuse, cudaFuncAttributeMaxDynamicSharedMemorySize, FUSE_SMEM);

    // Launch order: 4th launch (ncu capture slot) = k_fuse.
    // Deps: fuse needs sg only; gemm needs fuse + wovr.
    k_qp<<<dim3(B_SZ, 8), 256>>>(q, Wq);
    k_sgp<<<dim3(B_SZ, 8), 256>>>(Wkv);
    k_sgr<<<B_SZ, 256>>>(g);
    k_fuse<<<B_SZ * (HW / 8), 256, FUSE_SMEM>>>(c);
    k_wovp<<<dim3(64, 16), 256>>>(Wo, Wkv);
    k_wovr<<<256, 256>>>(g);
    k_gemm<<<512, 256>>>(bo, out);
}

// round 6
// speedup vs baseline: 1.3387x; 1.3387x over previous
#include <cuda_runtime.h>
#include <cstdint>

#define C_DIM 256
#define N_TOK 8
#define D_DIM 512
#define HW    4096
#define B_SZ  4
#define EPS   1e-6f

// ---- persistent scratch ----
__device__ float g_qp[B_SZ * D_DIM];
__device__ float g_sgp[16][B_SZ * C_DIM];
__device__ float g_sg[B_SZ * C_DIM];
__device__ float g_wovp[16][C_DIM * C_DIM];
__device__ float g_wovgT[C_DIM * C_DIM];             // [ch][co]
__device__ float g_agg[(size_t)B_SZ * C_DIM * HW];   // 16MB

#define FMA2(d, a, b, c) \
    asm("fma.rn.f32x2 %0, %1, %2, %3;" : "=l"(d) : "l"(a), "l"(b), "l"(c))

// ---------------------------------------------------------------------------
__global__ void k_qp(const float* __restrict__ q, const float* __restrict__ Wq) {
    int b = blockIdx.x, dc = blockIdx.y;
    __shared__ float qs[C_DIM];
    int tid = threadIdx.x, warp = tid >> 5, lane = tid & 31;
    qs[tid] = q[b * C_DIM + tid];
    __syncthreads();
    #pragma unroll
    for (int i = 0; i < 8; ++i) {
        int d = dc * 64 + i * 8 + warp;
        float s = 0.f;
        #pragma unroll
        for (int k = 0; k < 8; ++k) s += __ldg(&Wq[d * C_DIM + lane + k * 32]) * qs[lane + k * 32];
        #pragma unroll
        for (int o = 16; o > 0; o >>= 1) s += __shfl_xor_sync(0xffffffffu, s, o);
        if (lane == 0) g_qp[b * D_DIM + d] = s;
    }
}

// sgp: 16 chunks of 32 d  (was 8x64 — still latency-bound)
__global__ void k_sgp(const float* __restrict__ Wkv) {
    int b = blockIdx.x, ck = blockIdx.y, tid = threadIdx.x;
    __shared__ float qps[32];
    if (tid < 32) qps[tid] = g_qp[b * D_DIM + ck * 32 + tid];
    __syncthreads();
    float a = 0.f;
    const float* wk = Wkv + (size_t)(ck * 32) * C_DIM + tid;
    #pragma unroll
    for (int d = 0; d < 32; ++d) a += __ldg(wk + (size_t)d * C_DIM) * qps[d];
    g_sgp[ck][b * C_DIM + tid] = a;
}

__global__ void k_sgr(const float* __restrict__ g) {
    int b = blockIdx.x, tid = threadIdx.x;
    float s = 0.f;
    #pragma unroll
    for (int i = 0; i < 16; ++i) s += g_sgp[i][b * C_DIM + tid];
    g_sg[b * C_DIM + tid] = s * g[tid] * rsqrtf((float)D_DIM);
}

__global__ void k_wovp(const float* __restrict__ Wo, const float* __restrict__ Wkv) {
    int co0 = blockIdx.x * 4, kc = blockIdx.y;
    __shared__ float wo_s[4][32];
    int tid = threadIdx.x;
    if (tid < 128) {
        int r = tid >> 5, cc = tid & 31;
        wo_s[r][cc] = __ldg(&Wo[(co0 + r) * D_DIM + kc * 32 + cc]);
    }
    __syncthreads();
    const float* wv = Wkv + (size_t)(D_DIM + kc * 32) * C_DIM + tid;
    float a0 = 0.f, a1 = 0.f, a2 = 0.f, a3 = 0.f;
    #pragma unroll
    for (int d = 0; d < 32; ++d) {
        float v = __ldg(wv + (size_t)d * C_DIM);
        a0 += wo_s[0][d] * v; a1 += wo_s[1][d] * v;
        a2 += wo_s[2][d] * v; a3 += wo_s[3][d] * v;
    }
    float* o = &g_wovp[kc][tid * C_DIM + co0];
    o[0] = a0; o[1] = a1; o[2] = a2; o[3] = a3;
}

__global__ void k_wovr(const float* __restrict__ g) {
    int idx = blockIdx.x * 256 + threadIdx.x;
    float s = 0.f;
    #pragma unroll
    for (int i = 0; i < 16; ++i) s += g_wovp[i][idx];
    g_wovgT[idx] = s * g[idx >> 8];
}

// ---------------------------------------------------------------------------
// k_fuse v2: NO smem staging of c. Block = 32 pixels of one batch.
//  Phase A: thread = (n,p). Streams c[b,n,:,p] (warp = 32 consecutive p:
//           fully-coalesced 128B lines). Computes ss + dot alone.
//  Softmax: per-thread from smem dots.
//  Phase B: thread = (8-ch group, 4-px group). Re-reads tile (L2-hot) with
//           full-line LDG.128; writes agg[ch][p] with full-line STG.128.
// ---------------------------------------------------------------------------
__global__ void __launch_bounds__(256) k_fuse(const float* __restrict__ c) {
    __shared__ float dots[N_TOK][32];
    __shared__ float invs[N_TOK][32];
    __shared__ float wgt[N_TOK][32];
    __shared__ float sg_s[C_DIM];

    int tid = threadIdx.x;
    int blk = blockIdx.x;
    int b = blk >> 7;                     // 128 blocks per batch
    int p0 = (blk & 127) * 32;

    sg_s[tid] = g_sg[b * C_DIM + tid];
    __syncthreads();

    const float* cb = c + (size_t)b * N_TOK * C_DIM * HW;

    // ---- Phase A ----
    {
        int n = tid >> 5, p = tid & 31;
        const float* base = cb + (size_t)n * C_DIM * HW + p0 + p;
        float ss = 0.f, dt = 0.f;
        #pragma unroll 4
        for (int ch0 = 0; ch0 < C_DIM; ch0 += 4) {
            float4 s4 = *(const float4*)&sg_s[ch0];
            float v0 = __ldg(base + (size_t)(ch0 + 0) * HW);
            float v1 = __ldg(base + (size_t)(ch0 + 1) * HW);
            float v2 = __ldg(base + (size_t)(ch0 + 2) * HW);
            float v3 = __ldg(base + (size_t)(ch0 + 3) * HW);
            ss += v0 * v0 + v1 * v1 + v2 * v2 + v3 * v3;
            dt += v0 * s4.x + v1 * s4.y + v2 * s4.z + v3 * s4.w;
        }
        float inv = rsqrtf(ss * (1.0f / C_DIM) + EPS);
        dots[n][p] = dt * inv;
        invs[n][p] = inv;
    }
    __syncthreads();

    // ---- softmax (every thread computes its own (n,p) weight) ----
    {
        int n = tid >> 5, p = tid & 31;
        float m = dots[0][p];
        #pragma unroll
        for (int i = 1; i < N_TOK; ++i) m = fmaxf(m, dots[i][p]);
        float sum = 0.f;
        #pragma unroll
        for (int i = 0; i < N_TOK; ++i) sum += __expf(dots[i][p] - m);
        wgt[n][p] = __expf(dots[n][p] - m) / sum * invs[n][p];
    }
    __syncthreads();

    // ---- Phase B: re-read tile (L2), aggregate over n ----
    {
        int p4 = tid & 7;                 // 4-pixel group
        int chg = tid >> 3;               // 8-channel group (0..31)
        int ch0 = chg * 8;
        float4 acc[8];
        #pragma unroll
        for (int j = 0; j < 8; ++j) acc[j] = make_float4(0.f, 0.f, 0.f, 0.f);

        #pragma unroll
        for (int n = 0; n < N_TOK; ++n) {
            float4 w4 = *(const float4*)&wgt[n][p4 * 4];
            const float* rn = cb + (size_t)(n * C_DIM + ch0) * HW + p0 + p4 * 4;
            #pragma unroll
            for (int j = 0; j < 8; ++j) {
                float4 v = __ldg((const float4*)(rn + (size_t)j * HW));
                acc[j].x += w4.x * v.x; acc[j].y += w4.y * v.y;
                acc[j].z += w4.z * v.z; acc[j].w += w4.w * v.w;
            }
        }
        float* ag = g_agg + (size_t)(b * C_DIM + ch0) * HW + p0 + p4 * 4;
        #pragma unroll
        for (int j = 0; j < 8; ++j)
            *(float4*)(ag + (size_t)j * HW) = acc[j];
    }
}

// ---------------------------------------------------------------------------
// k_gemm: 64co x 128p tiles, K=32 chunks, double-buffered, FFMA2.
// (inner loop reverted to R4/177.6 form — LDS.64 broadcast weights)
// ---------------------------------------------------------------------------
#define TP  128
#define TCO 64
#define KC  32
__global__ void __launch_bounds__(256) k_gemm(const float* __restrict__ bo,
                                              float* __restrict__ out) {
    __shared__ float aggS[2][KC][TP];
    __shared__ unsigned long long wovD[2][KC][TCO];
    int tid = threadIdx.x;
    int blk = blockIdx.x;
    int pt = blk & 31, ct = (blk >> 5) & 3, b = blk >> 7;
    int p0 = pt * TP, co0 = ct * TCO;
    int tx = tid & 31, ty = tid >> 5;
    int po = tx * 4, coo = ty * 8;

    unsigned long long acc[8][2];
    #pragma unroll
    for (int i = 0; i < 8; ++i) { acc[i][0] = 0ull; acc[i][1] = 0ull; }

    const float* aggB = g_agg + (size_t)b * C_DIM * HW + p0;

    #define STAGE(BUF, CH0) do {                                               \
        _Pragma("unroll")                                                      \
        for (int k = 0; k < 4; ++k) {                                          \
            int idx = tid + k * 256;                                           \
            int ch = idx >> 5, f = idx & 31;                                   \
            *(float4*)&aggS[BUF][ch][f * 4] =                                  \
                __ldg((const float4*)(aggB + (size_t)((CH0) + ch) * HW) + f);  \
        }                                                                      \
        _Pragma("unroll")                                                      \
        for (int k = 0; k < 8; ++k) {                                          \
            int idx = tid + k * 256;                                           \
            int ch = idx >> 6, co = idx & 63;                                  \
            float w = __ldg(&g_wovgT[((CH0) + ch) * C_DIM + co0 + co]);        \
            unsigned long long pk;                                             \
            asm("mov.b64 %0, {%1, %1};" : "=l"(pk) : "r"(__float_as_uint(w))); \
            wovD[BUF][ch][co] = pk;                                            \
        }                                                                      \
    } while (0)

    STAGE(0, 0);
    #pragma unroll
    for (int ck = 0; ck < 8; ++ck) {
        __syncthreads();
        if (ck < 7) STAGE((ck + 1) & 1, (ck + 1) * KC);
        int cur = ck & 1;
        #pragma unroll
        for (int ch = 0; ch < KC; ++ch) {
            ulonglong2 ap = *(const ulonglong2*)&aggS[cur][ch][po];
            const unsigned long long* wp = &wovD[cur][ch][coo];
            #pragma unroll
            for (int i = 0; i < 8; ++i) {
                FMA2(acc[i][0], wp[i], ap.x, acc[i][0]);
                FMA2(acc[i][1], wp[i], ap.y, acc[i][1]);
            }
        }
    }
    #undef STAGE

    float* ob = out + ((size_t)b * C_DIM + co0 + coo) * HW + p0 + po;
    #pragma unroll
    for (int i = 0; i < 8; ++i) {
        float bb = __ldg(&bo[co0 + coo + i]);
        unsigned lx, ly, hx, hy;
        asm("mov.b64 {%0, %1}, %2;" : "=r"(lx), "=r"(ly) : "l"(acc[i][0]));
        asm("mov.b64 {%0, %1}, %2;" : "=r"(hx), "=r"(hy) : "l"(acc[i][1]));
        float4 r = make_float4(__uint_as_float(lx) + bb, __uint_as_float(ly) + bb,
                               __uint_as_float(hx) + bb, __uint_as_float(hy) + bb);
        *(float4*)(ob + (size_t)i * HW) = r;
    }
}

extern "C" void kernel_launch(void* const* d_in, const int* in_sizes, int n_in,
                              void* d_out, int out_size) {
    const float* q   = (const float*)d_in[0];
    const float* c   = (const float*)d_in[1];
    const float* g   = (const float*)d_in[2];
    const float* Wq  = (const float*)d_in[3];
    const float* Wkv = (const float*)d_in[4];
    const float* Wo  = (const float*)d_in[5];
    const float* bo  = (const float*)d_in[6];
    float* out = (float*)d_out;

    // 4th launch = k_fuse (ncu capture slot)
    k_qp<<<dim3(B_SZ, 8), 256>>>(q, Wq);
    k_sgp<<<dim3(B_SZ, 16), 256>>>(Wkv);
    k_sgr<<<B_SZ, 256>>>(g);
    k_fuse<<<B_SZ * (HW / 32), 256>>>(c);
    k_wovp<<<dim3(64, 16), 256>>>(Wo, Wkv);
    k_wovr<<<256, 256>>>(g);
    k_gemm<<<512, 256>>>(bo, out);
}